// round 5
// baseline (speedup 1.0000x reference)
#include <cuda_runtime.h>

// Problem constants
#define NN 4
#define CC 256
#define HW 20480            // 128*160
#define PP (NN*HW)          // 81920 pixels
#define NB 64               // depth bins
#define CHUNK 10240         // pixels per block (2 chunks per n-plane)
#define CHUNKS_PER_PLANE (HW/CHUNK)   // 2
#define NCHUNKS (PP/CHUNK)            // 8
#define CGROUPS (CC/8)                // 32 channel groups (8 channels/block)

// Scratch (no device allocation allowed -> __device__ globals)
__device__ unsigned char g_idx[PP];
__device__ float g_counts[NB];
__device__ float g_sums[2*NB*CC];     // [tensor][bin][channel]
__device__ float g_protos[2*NB*CC];   // normalized prototypes

// ---------------------------------------------------------------------------
// K0: zero scratch + output
__global__ void k0_zero(float* out) {
    int i = blockIdx.x * blockDim.x + threadIdx.x;
    if (i < 2*NB*CC) g_sums[i] = 0.f;
    if (i < NB)      g_counts[i] = 0.f;
    if (i == 0)      out[0] = 0.f;
}

// ---------------------------------------------------------------------------
// K1: bin index per pixel (uint8) + per-bin counts
__device__ __forceinline__ unsigned char bin_of(float d) {
    float t = d * 64.0f;                       // bin_size = 1/64 exactly
    // valid iff 0 <= t < 64 (t==64 or invalid/NaN -> overflow bin 64)
    if (t >= 0.0f && t < 64.0f) return (unsigned char)(int)t;  // trunc == ref
    return (unsigned char)64;
}

__global__ void k1_idx(const float* __restrict__ depth) {
    __shared__ int hist[NB];
    int tid = threadIdx.x;
    if (tid < NB) hist[tid] = 0;
    __syncthreads();

    int g = blockIdx.x * blockDim.x + tid;     // 80*256 = 20480 float4s = 81920 px
    float4 d = ((const float4*)depth)[g];
    uchar4 b4;
    b4.x = bin_of(d.x); b4.y = bin_of(d.y); b4.z = bin_of(d.z); b4.w = bin_of(d.w);
    ((uchar4*)g_idx)[g] = b4;
    if (b4.x < 64) atomicAdd(&hist[b4.x], 1);
    if (b4.y < 64) atomicAdd(&hist[b4.y], 1);
    if (b4.z < 64) atomicAdd(&hist[b4.z], 1);
    if (b4.w < 64) atomicAdd(&hist[b4.w], 1);
    __syncthreads();
    if (tid < NB && hist[tid] != 0) atomicAdd(&g_counts[tid], (float)hist[tid]);
}

// ---------------------------------------------------------------------------
// K2: main streaming segment-sum.
// Block = 8 warps = 8 channels of one channel-group; warp lanes stream pixels.
// Private smem accumulator column per thread: acc[bin][tid] -> no atomics, no
// bank conflicts (bank = tid%32), race-free RMW.
__global__ void __launch_bounds__(256) k2_accum(const float* __restrict__ S,
                                                const float* __restrict__ T) {
    extern __shared__ float acc[];             // [NB][256] = 64 KB
    const int tid  = threadIdx.x;
    const int warp = tid >> 5;
    const int lane = tid & 31;
    const int chunk = blockIdx.x;              // 0..7
    const int n   = chunk / CHUNKS_PER_PLANE;
    const int hw0 = (chunk % CHUNKS_PER_PLANE) * CHUNK;
    const int c   = blockIdx.y * 8 + warp;     // this warp's channel

    const unsigned char* __restrict__ ib = g_idx + n*HW + hw0;
    const long base_off = ((long)(n*CC + c))*HW + hw0;

    for (int t = 0; t < 2; ++t) {
        const float* __restrict__ src = (t == 0 ? S : T) + base_off;

        for (int i = tid; i < NB*256; i += 256) acc[i] = 0.f;
        __syncthreads();

        #pragma unroll 4
        for (int it = 0; it < CHUNK/128; ++it) {   // 80 iters
            int p = it*128 + lane*4;
            float4 v  = *(const float4*)(src + p);
            uchar4 b4 = *(const uchar4*)(ib + p);
            if (b4.x < 64) acc[(int)b4.x*256 + tid] += v.x;
            if (b4.y < 64) acc[(int)b4.y*256 + tid] += v.y;
            if (b4.z < 64) acc[(int)b4.z*256 + tid] += v.z;
            if (b4.w < 64) acc[(int)b4.w*256 + tid] += v.w;
        }
        __syncthreads();

        // warp-reduce the 32 lane-partials of this warp's channel, per bin
        float* dst = g_sums + (t*NB)*CC + c;
        for (int b = 0; b < NB; ++b) {
            float v = acc[b*256 + tid];
            v += __shfl_down_sync(0xffffffffu, v, 16);
            v += __shfl_down_sync(0xffffffffu, v, 8);
            v += __shfl_down_sync(0xffffffffu, v, 4);
            v += __shfl_down_sync(0xffffffffu, v, 2);
            v += __shfl_down_sync(0xffffffffu, v, 1);
            if (lane == 0) atomicAdd(dst + b*CC, v);
        }
        __syncthreads();
    }
}

// ---------------------------------------------------------------------------
// K3a: means -> L2-normalized prototypes. Block per (tensor, bin).
__global__ void k3a_protos() {
    const int t = blockIdx.x >> 6;
    const int b = blockIdx.x & 63;
    const int tid = threadIdx.x;               // 128 threads
    __shared__ float warpred[4];

    float cnt = fmaxf(g_counts[b], 1.0f);
    float inv_cnt = 1.0f / cnt;
    const float* s = g_sums + (t*NB + b)*CC;
    float m0 = s[tid]       * inv_cnt;
    float m1 = s[tid + 128] * inv_cnt;

    float ss = m0*m0 + m1*m1;
    #pragma unroll
    for (int o = 16; o; o >>= 1) ss += __shfl_down_sync(0xffffffffu, ss, o);
    if ((tid & 31) == 0) warpred[tid >> 5] = ss;
    __syncthreads();
    float tot = warpred[0] + warpred[1] + warpred[2] + warpred[3];
    float inv = 1.0f / fmaxf(sqrtf(tot), 1e-12f);

    float* p = g_protos + (t*NB + b)*CC;
    p[tid]       = m0 * inv;
    p[tid + 128] = m1 * inv;
}

// ---------------------------------------------------------------------------
// K3b: loss = mean((pS pS^T - pT pT^T)^2). Block per row i; warp per 8 cols.
__global__ void k3b_loss(float* __restrict__ out) {
    const int i   = blockIdx.x;                // 0..63
    const int tid = threadIdx.x;               // 256
    __shared__ float pSi[CC], pTi[CC];
    pSi[tid] = g_protos[i*CC + tid];
    pTi[tid] = g_protos[(NB + i)*CC + tid];
    __syncthreads();

    const int warp = tid >> 5, lane = tid & 31;
    for (int jj = 0; jj < 8; ++jj) {
        int j = warp*8 + jj;
        const float* __restrict__ qS = g_protos + j*CC;
        const float* __restrict__ qT = g_protos + (NB + j)*CC;
        float sS = 0.f, sT = 0.f;
        #pragma unroll
        for (int k = lane; k < CC; k += 32) {
            sS += pSi[k] * qS[k];
            sT += pTi[k] * qT[k];
        }
        #pragma unroll
        for (int o = 16; o; o >>= 1) {
            sS += __shfl_down_sync(0xffffffffu, sS, o);
            sT += __shfl_down_sync(0xffffffffu, sT, o);
        }
        if (lane == 0) {
            float d = sS - sT;
            atomicAdd(out, d * d * (1.0f / (NB * NB)));
        }
    }
}

// ---------------------------------------------------------------------------
extern "C" void kernel_launch(void* const* d_in, const int* in_sizes, int n_in,
                              void* d_out, int out_size) {
    (void)in_sizes; (void)n_in; (void)out_size;
    const float* S     = (const float*)d_in[0];
    const float* T     = (const float*)d_in[1];
    const float* depth = (const float*)d_in[2];
    float* out = (float*)d_out;

    cudaFuncSetAttribute(k2_accum, cudaFuncAttributeMaxDynamicSharedMemorySize,
                         NB * 256 * (int)sizeof(float));

    k0_zero<<<128, 256>>>(out);
    k1_idx<<<80, 256>>>(depth);
    k2_accum<<<dim3(NCHUNKS, CGROUPS), 256, NB*256*sizeof(float)>>>(S, T);
    k3a_protos<<<2*NB, 128>>>();
    k3b_loss<<<NB, 256>>>(out);
}

// round 6
// speedup vs baseline: 1.1168x; 1.1168x over previous
#include <cuda_runtime.h>

// Problem constants
#define NN 4
#define CC 256
#define HW 20480            // 128*160
#define PP (NN*HW)          // 81920 pixels
#define NB 64               // depth bins
#define CHUNK 10240         // pixels per block chunk
#define NCHUNKS (PP/CHUNK)  // 8
#define K1_BLOCKS 80

// Scratch (no device allocation allowed -> __device__ globals)
__device__ unsigned char g_idx[PP];
__device__ int   g_hist[K1_BLOCKS*NB];   // per-k1-block histogram partials
__device__ float g_sums[2*NB*CC];        // [tensor][bin][channel]

// ---------------------------------------------------------------------------
// K1: bin index per pixel (uint8) + per-block histogram partials
//     + zero g_sums and out (safe: partials are non-atomic, sums zeroed here
//       are only touched by the NEXT kernel).
__device__ __forceinline__ unsigned char bin_of(float d) {
    float t = d * 64.0f;                       // bin_size = 1/64 exactly
    if (t >= 0.0f && t < 64.0f) return (unsigned char)(int)t;  // trunc == ref
    return (unsigned char)64;                  // overflow/invalid bin
}

__global__ void __launch_bounds__(256) k1_idx(const float* __restrict__ depth,
                                              float* __restrict__ out) {
    __shared__ int hist[NB];
    const int tid = threadIdx.x;
    if (tid < NB) hist[tid] = 0;
    __syncthreads();

    const int g = blockIdx.x * 256 + tid;      // 80*256 = 20480 float4s
    float4 d = ((const float4*)depth)[g];
    uchar4 b4;
    b4.x = bin_of(d.x); b4.y = bin_of(d.y); b4.z = bin_of(d.z); b4.w = bin_of(d.w);
    ((uchar4*)g_idx)[g] = b4;
    if (b4.x < 64) atomicAdd(&hist[b4.x], 1);
    if (b4.y < 64) atomicAdd(&hist[b4.y], 1);
    if (b4.z < 64) atomicAdd(&hist[b4.z], 1);
    if (b4.w < 64) atomicAdd(&hist[b4.w], 1);

    // zero scratch consumed by later kernels
    for (int i = g; i < 2*NB*CC; i += K1_BLOCKS*256) g_sums[i] = 0.f;
    if (g == 0) out[0] = 0.f;

    __syncthreads();
    if (tid < NB) g_hist[blockIdx.x*NB + tid] = hist[tid];
}

// ---------------------------------------------------------------------------
// K2: streaming segment-sum.
// Block = 128 threads = 4 warps = 4 channels; warp lanes stream pixels.
// grid = (chunk 0..7, cgroup 0..63, tensor 0..1)  -> 1024 blocks, 32KB smem,
// 6-7 blocks/SM. Private smem column per thread: acc[bin][tid] (bank = tid%32,
// conflict-free, race-free RMW, no atomics in the hot loop).
__global__ void __launch_bounds__(128) k2_accum(const float* __restrict__ S,
                                                const float* __restrict__ T) {
    extern __shared__ float acc[];             // [NB][128] = 32 KB
    const int tid  = threadIdx.x;
    const int warp = tid >> 5;
    const int lane = tid & 31;
    const int chunk = blockIdx.x;              // 0..7
    const int n   = chunk >> 1;
    const int hw0 = (chunk & 1) * CHUNK;
    const int c   = blockIdx.y * 4 + warp;     // this warp's channel

    const unsigned char* __restrict__ ib = g_idx + n*HW + hw0;
    const float* __restrict__ src =
        (blockIdx.z ? T : S) + ((long)(n*CC + c))*HW + hw0;

    for (int i = tid; i < NB*128; i += 128) acc[i] = 0.f;
    __syncthreads();

    #pragma unroll 2
    for (int it = 0; it < CHUNK/256; ++it) {   // 40 iters, 8 px/lane/iter
        const int p = it*256 + lane*4;
        float4 v0 = *(const float4*)(src + p);
        float4 v1 = *(const float4*)(src + p + 128);
        uchar4 b0 = *(const uchar4*)(ib + p);
        uchar4 b1 = *(const uchar4*)(ib + p + 128);
        if (b0.x < 64) acc[(int)b0.x*128 + tid] += v0.x;
        if (b0.y < 64) acc[(int)b0.y*128 + tid] += v0.y;
        if (b0.z < 64) acc[(int)b0.z*128 + tid] += v0.z;
        if (b0.w < 64) acc[(int)b0.w*128 + tid] += v0.w;
        if (b1.x < 64) acc[(int)b1.x*128 + tid] += v1.x;
        if (b1.y < 64) acc[(int)b1.y*128 + tid] += v1.y;
        if (b1.z < 64) acc[(int)b1.z*128 + tid] += v1.z;
        if (b1.w < 64) acc[(int)b1.w*128 + tid] += v1.w;
    }
    __syncthreads();

    // Tail reduce: lane l sums bins l and l+32 across this warp's 32 columns.
    // Rotation (j+lane)&31 keeps all lanes on distinct banks every step.
    const float* aw = acc + warp*32;
    float s0 = 0.f, s1 = 0.f;
    #pragma unroll
    for (int j = 0; j < 32; ++j) {
        const int col = (j + lane) & 31;
        s0 += aw[lane*128 + col];
        s1 += aw[(lane + 32)*128 + col];
    }
    float* dst = g_sums + blockIdx.z*NB*CC + c;
    atomicAdd(dst + lane*CC,        s0);
    atomicAdd(dst + (lane + 32)*CC, s1);
}

// ---------------------------------------------------------------------------
// K3 (fused protos + loss): 64 blocks. Each block normalizes ALL 128 protos
// into its own smem (g_sums is L2-resident, 8 MB chip-wide re-read), then
// computes Gram row i for S and T and accumulates the squared difference.
__global__ void __launch_bounds__(256) k3_loss(float* __restrict__ out) {
    extern __shared__ float prot[];            // [2*NB][CC] = 128 KB
    __shared__ float inv_cnt[NB];
    const int tid = threadIdx.x, warp = tid >> 5, lane = tid & 31;

    // counts from k1 partials
    if (tid < NB) {
        int cnt = 0;
        for (int p = 0; p < K1_BLOCKS; ++p) cnt += g_hist[p*NB + tid];
        inv_cnt[tid] = 1.0f / fmaxf((float)cnt, 1.0f);
    }
    __syncthreads();

    // normalize all 128 (tensor,bin) rows; warp per row
    for (int r = warp; r < 2*NB; r += 8) {
        const float* __restrict__ s = g_sums + r*CC;
        const float ic = inv_cnt[r & 63];
        float m[8]; float ss = 0.f;
        #pragma unroll
        for (int k = 0; k < 8; ++k) { m[k] = s[lane + 32*k] * ic; ss += m[k]*m[k]; }
        #pragma unroll
        for (int o = 16; o; o >>= 1) ss += __shfl_xor_sync(0xffffffffu, ss, o);
        const float inv = 1.0f / fmaxf(sqrtf(ss), 1e-12f);
        #pragma unroll
        for (int k = 0; k < 8; ++k) prot[r*CC + lane + 32*k] = m[k] * inv;
    }
    __syncthreads();

    // Gram row i: loss contribution sum_j (pSi.pSj - pTi.pTj)^2
    const int i = blockIdx.x;
    const float* pSi = prot + i*CC;
    const float* pTi = prot + (NB + i)*CC;
    float accv = 0.f;
    for (int j = warp; j < NB; j += 8) {
        const float* qS = prot + j*CC;
        const float* qT = prot + (NB + j)*CC;
        float sS = 0.f, sT = 0.f;
        #pragma unroll
        for (int k = lane; k < CC; k += 32) { sS += pSi[k]*qS[k]; sT += pTi[k]*qT[k]; }
        #pragma unroll
        for (int o = 16; o; o >>= 1) {
            sS += __shfl_xor_sync(0xffffffffu, sS, o);
            sT += __shfl_xor_sync(0xffffffffu, sT, o);
        }
        if (lane == 0) { const float d = sS - sT; accv += d*d; }
    }
    if (lane == 0) atomicAdd(out, accv * (1.0f/(NB*NB)));
}

// ---------------------------------------------------------------------------
extern "C" void kernel_launch(void* const* d_in, const int* in_sizes, int n_in,
                              void* d_out, int out_size) {
    (void)in_sizes; (void)n_in; (void)out_size;
    const float* S     = (const float*)d_in[0];
    const float* T     = (const float*)d_in[1];
    const float* depth = (const float*)d_in[2];
    float* out = (float*)d_out;

    cudaFuncSetAttribute(k3_loss, cudaFuncAttributeMaxDynamicSharedMemorySize,
                         2*NB*CC*(int)sizeof(float));

    k1_idx<<<K1_BLOCKS, 256>>>(depth, out);
    k2_accum<<<dim3(NCHUNKS, CC/4, 2), 128, NB*128*sizeof(float)>>>(S, T);
    k3_loss<<<NB, 256, 2*NB*CC*sizeof(float)>>>(out);
}